// round 6
// baseline (speedup 1.0000x reference)
#include <cuda_runtime.h>
#include <cuda_bf16.h>

#define MODIFIER_COL 11
#define OWNER_COL    24
#define MAXG         8192
#define F_DIM        128

// Persistent scratch (no cudaMalloc allowed). Zero-initialized at load; the
// last block resets the used range after consuming it, so each graph replay
// starts clean (deterministic).
__device__ float g_cnt[MAXG];
__device__ float g_s0[MAXG];
__device__ float g_s1[MAXG];
__device__ unsigned int g_done;

// R2's proven reduce body (1 row/thread, warp segreduce over sorted keys,
// ~1 atomic triple per warp-segment) + last-block-done finalize where the
// gpu-scope fence is executed by ONE thread per block (fence cumulativity
// makes this correct: bar.sync is cta-scope cumulative, membar.gl chains it).
__global__ __launch_bounds__(256) void fused_kernel(
    const float* __restrict__ nf,
    const int*   __restrict__ batch,
    const float* __restrict__ W1,   // [32,2] row-major
    const float* __restrict__ b1,   // [32]
    const float* __restrict__ W2,   // [1,32]
    const float* __restrict__ b2,   // [1]
    float* __restrict__ out,
    int N, int G)
{
    const int i    = blockIdx.x * blockDim.x + threadIdx.x;
    const int lane = threadIdx.x & 31;

    int   g  = -1;
    float c  = 0.f, v0 = 0.f, v1 = 0.f;
    if (i < N) {
        g  = batch[i];
        const float* row = nf + (size_t)i * F_DIM;
        v0 = __ldg(row + MODIFIER_COL);
        v1 = __ldg(row + OWNER_COL);
        c  = 1.f;
    }

    // Down-sweep segmented reduction (keys non-decreasing across lanes).
    #pragma unroll
    for (int d = 1; d < 32; d <<= 1) {
        int   go = __shfl_down_sync(0xffffffffu, g,  d);
        float co = __shfl_down_sync(0xffffffffu, c,  d);
        float a0 = __shfl_down_sync(0xffffffffu, v0, d);
        float a1 = __shfl_down_sync(0xffffffffu, v1, d);
        if (lane + d < 32 && go == g) { c += co; v0 += a0; v1 += a1; }
    }

    int  gprev = __shfl_up_sync(0xffffffffu, g, 1);
    bool head  = (lane == 0) || (gprev != g);
    if (head && g >= 0 && g < MAXG) {
        atomicAdd(&g_cnt[g], c);
        atomicAdd(&g_s0[g],  v0);
        atomicAdd(&g_s1[g],  v1);
    }

    // ---- last-block-done: ONE fence per block, not one per thread ---------
    __syncthreads();                       // block's atomics visible (cta-scope, cumulative)
    __shared__ bool is_last;
    if (threadIdx.x == 0) {
        __threadfence();                   // release: chains block's atomics to gpu scope
        unsigned int prev = atomicAdd(&g_done, 1u);
        is_last = (prev == gridDim.x - 1);
        if (is_last) __threadfence();      // acquire: all blocks' atomics now ordered-before our reads
    }
    __syncthreads();                       // broadcast is_last + acquire to whole block
    if (!is_last) return;

    // ---- finalize: 2048-graph MLP + scratch reset, in the last block ------
    for (int gg = threadIdx.x; gg < G; gg += blockDim.x) {
        float cc = __ldcg(&g_cnt[gg]);     // L2-only reads (values live at L2)
        float t0 = __ldcg(&g_s0[gg]);
        float t1 = __ldcg(&g_s1[gg]);
        g_cnt[gg] = 0.f; g_s0[gg] = 0.f; g_s1[gg] = 0.f;   // reset for replay

        float denom = fmaxf(cc, 1.f);
        float f0 = 1.f - t0 / denom;
        float f1 = 1.f - t1 / denom;

        float acc = __ldg(b2);
        #pragma unroll
        for (int j = 0; j < 32; ++j) {
            float h = fmaf(f0, __ldg(W1 + 2 * j),
                      fmaf(f1, __ldg(W1 + 2 * j + 1), __ldg(b1 + j)));
            h   = fmaxf(h, 0.f);
            acc = fmaf(__ldg(W2 + j), h, acc);
        }
        float score = 1.f / (1.f + __expf(-acc));
        out[gg] = (cc > 0.f) ? score : 0.f;
    }
    __syncthreads();
    if (threadIdx.x == 0) g_done = 0u;     // reset counter for next replay
}

extern "C" void kernel_launch(void* const* d_in, const int* in_sizes, int n_in,
                              void* d_out, int out_size)
{
    // order: node_features, batch, graph_embedding, W1, b1, W2, b2
    const float* nf    = (const float*)d_in[0];
    const int*   batch = (const int*)d_in[1];
    const float* W1    = (const float*)d_in[3];
    const float* b1    = (const float*)d_in[4];
    const float* W2    = (const float*)d_in[5];
    const float* b2    = (const float*)d_in[6];
    float*       out   = (float*)d_out;

    int N = in_sizes[1];
    int G = in_sizes[2] / F_DIM;
    if (G <= 0 || G > MAXG) G = out_size;

    int blocks = (N + 255) / 256;
    fused_kernel<<<blocks, 256>>>(nf, batch, W1, b1, W2, b2, out, N, G);
}

// round 7
// speedup vs baseline: 1.4242x; 1.4242x over previous
#include <cuda_runtime.h>
#include <cuda_bf16.h>

#define MODIFIER_COL 11
#define OWNER_COL    24
#define MAXG         8192
#define F_DIM        128

// Persistent scratch (no cudaMalloc allowed). Zero-initialized at load;
// finalize_kernel resets the used range after consuming it, so each graph
// replay starts clean (deterministic).
__device__ float g_cnt[MAXG];
__device__ float g_s0[MAXG];
__device__ float g_s1[MAXG];

// ---- R2's proven reduce: 1 row/thread, warp segreduce over sorted keys,
// ~1 atomic triple per warp-segment. Runs at ~6.3TB/s on the mandatory
// 136MB (128B/row DRAM-burst floor). ----
__global__ __launch_bounds__(256) void reduce_kernel(
    const float* __restrict__ nf,
    const int*   __restrict__ batch,
    int N)
{
    const int i    = blockIdx.x * blockDim.x + threadIdx.x;
    const int lane = threadIdx.x & 31;

    int   g  = -1;
    float c  = 0.f, v0 = 0.f, v1 = 0.f;
    if (i < N) {
        g  = batch[i];
        const float* row = nf + (size_t)i * F_DIM;
        v0 = __ldg(row + MODIFIER_COL);
        v1 = __ldg(row + OWNER_COL);
        c  = 1.f;
    }

    // Down-sweep segmented reduction (keys non-decreasing across lanes).
    #pragma unroll
    for (int d = 1; d < 32; d <<= 1) {
        int   go = __shfl_down_sync(0xffffffffu, g,  d);
        float co = __shfl_down_sync(0xffffffffu, c,  d);
        float a0 = __shfl_down_sync(0xffffffffu, v0, d);
        float a1 = __shfl_down_sync(0xffffffffu, v1, d);
        if (lane + d < 32 && go == g) { c += co; v0 += a0; v1 += a1; }
    }

    int  gprev = __shfl_up_sync(0xffffffffu, g, 1);
    bool head  = (lane == 0) || (gprev != g);
    if (head && g >= 0 && g < MAXG) {
        atomicAdd(&g_cnt[g], c);
        atomicAdd(&g_s0[g],  v0);
        atomicAdd(&g_s1[g],  v1);
    }

#if __CUDA_ARCH__ >= 900
    // Release the PDL-dependent finalize launch as early as possible; its
    // gridDependencySynchronize still waits for our full completion.
    cudaTriggerProgrammaticLaunchCompletion();
#endif
}

// ---- Finalize with PDL: the prologue (launch + cold weight staging into
// SMEM) overlaps the reduce's tail; only the post-sync part is serialized. --
__global__ __launch_bounds__(128) void finalize_kernel(
    const float* __restrict__ W1,   // [32,2] row-major
    const float* __restrict__ b1,   // [32]
    const float* __restrict__ W2,   // [1,32]
    const float* __restrict__ b2,   // [1]
    float* __restrict__ out,
    int G)
{
    __shared__ float sW1[64];
    __shared__ float sb1[32];
    __shared__ float sW2[32];
    __shared__ float sb2;

    const int t = threadIdx.x;
    // Independent of the reduce: issue BEFORE the grid-dependency sync so the
    // cold DRAM fetch of the weights overlaps the reduce's tail.
    if (t < 64)        sW1[t]      = W1[t];
    else if (t < 96)   sb1[t - 64] = b1[t - 64];
    else               sW2[t - 96] = W2[t - 96];
    if (t == 0)        sb2 = *b2;

#if __CUDA_ARCH__ >= 900
    cudaGridDependencySynchronize();   // reduce fully done + memory visible
#endif
    __syncthreads();

    int g = blockIdx.x * blockDim.x + t;
    if (g >= G) return;

    float cc = g_cnt[g];
    float t0 = g_s0[g];
    float t1 = g_s1[g];
    g_cnt[g] = 0.f; g_s0[g] = 0.f; g_s1[g] = 0.f;   // reset for next replay

    float denom = fmaxf(cc, 1.f);
    float f0 = 1.f - t0 / denom;
    float f1 = 1.f - t1 / denom;

    float acc = sb2;
    #pragma unroll
    for (int j = 0; j < 32; ++j) {
        float h = fmaf(f0, sW1[2 * j], fmaf(f1, sW1[2 * j + 1], sb1[j]));
        h   = fmaxf(h, 0.f);
        acc = fmaf(sW2[j], h, acc);
    }
    float score = 1.f / (1.f + __expf(-acc));
    out[g] = (cc > 0.f) ? score : 0.f;
}

extern "C" void kernel_launch(void* const* d_in, const int* in_sizes, int n_in,
                              void* d_out, int out_size)
{
    // order: node_features, batch, graph_embedding, W1, b1, W2, b2
    const float* nf    = (const float*)d_in[0];
    const int*   batch = (const int*)d_in[1];
    const float* W1    = (const float*)d_in[3];
    const float* b1    = (const float*)d_in[4];
    const float* W2    = (const float*)d_in[5];
    const float* b2    = (const float*)d_in[6];
    float*       out   = (float*)d_out;

    int N = in_sizes[1];
    int G = in_sizes[2] / F_DIM;
    if (G <= 0 || G > MAXG) G = out_size;

    int rb = (N + 255) / 256;
    reduce_kernel<<<rb, 256>>>(nf, batch, N);

    // PDL launch: finalize may begin its prologue while reduce drains.
    int fb = (G + 127) / 128;
    cudaLaunchConfig_t cfg = {};
    cfg.gridDim  = dim3((unsigned)fb, 1, 1);
    cfg.blockDim = dim3(128, 1, 1);
    cfg.dynamicSmemBytes = 0;
    cfg.stream = 0;   // same (legacy default) stream the <<<>>> launch used
    cudaLaunchAttribute attr[1];
    attr[0].id = cudaLaunchAttributeProgrammaticStreamSerialization;
    attr[0].val.programmaticStreamSerializationAllowed = 1;
    cfg.attrs = attr;
    cfg.numAttrs = 1;
    cudaLaunchKernelEx(&cfg, finalize_kernel, W1, b1, W2, b2, out, G);
}

// round 8
// speedup vs baseline: 1.4987x; 1.0523x over previous
#include <cuda_runtime.h>
#include <cuda_bf16.h>

#define MODIFIER_COL 11
#define OWNER_COL    24
#define MAXG         8192
#define F_DIM        128

// Persistent scratch (no cudaMalloc allowed). Zero-initialized at load;
// finalize_kernel resets the used range after consuming it, so each graph
// replay starts clean (deterministic).
__device__ float g_cnt[MAXG];
__device__ float g_s0[MAXG];
__device__ float g_s1[MAXG];

// ---- R2's proven reduce: 1 row/thread, warp segreduce over sorted keys,
// ~1 atomic triple per warp-segment. Runs at ~6.1TB/s on the mandatory
// 132MB (two 64B HBM atoms per 512B row -> 128B/row floor). ----
__global__ __launch_bounds__(256) void reduce_kernel(
    const float* __restrict__ nf,
    const int*   __restrict__ batch,
    int N)
{
#if __CUDA_ARCH__ >= 900
    // Trigger FIRST: the dependent finalize may begin its prologue (launch
    // ramp + cold weight staging) as soon as every CTA has started — i.e.,
    // under our last wave. Its gridDependencySynchronize still waits for our
    // full completion + memory visibility, so this is correctness-neutral.
    cudaTriggerProgrammaticLaunchCompletion();
#endif

    const int i    = blockIdx.x * blockDim.x + threadIdx.x;
    const int lane = threadIdx.x & 31;

    int   g  = -1;
    float c  = 0.f, v0 = 0.f, v1 = 0.f;
    if (i < N) {
        g  = batch[i];
        const float* row = nf + (size_t)i * F_DIM;
        v0 = __ldg(row + MODIFIER_COL);
        v1 = __ldg(row + OWNER_COL);
        c  = 1.f;
    }

    // Down-sweep segmented reduction (keys non-decreasing across lanes).
    #pragma unroll
    for (int d = 1; d < 32; d <<= 1) {
        int   go = __shfl_down_sync(0xffffffffu, g,  d);
        float co = __shfl_down_sync(0xffffffffu, c,  d);
        float a0 = __shfl_down_sync(0xffffffffu, v0, d);
        float a1 = __shfl_down_sync(0xffffffffu, v1, d);
        if (lane + d < 32 && go == g) { c += co; v0 += a0; v1 += a1; }
    }

    int  gprev = __shfl_up_sync(0xffffffffu, g, 1);
    bool head  = (lane == 0) || (gprev != g);
    if (head && g >= 0 && g < MAXG) {
        atomicAdd(&g_cnt[g], c);
        atomicAdd(&g_s0[g],  v0);
        atomicAdd(&g_s1[g],  v1);
    }
}

// ---- Finalize with PDL: prologue (launch + weight staging into SMEM)
// overlaps the reduce's last wave; only the post-sync MLP is serialized. ----
__global__ __launch_bounds__(128) void finalize_kernel(
    const float* __restrict__ W1,   // [32,2] row-major
    const float* __restrict__ b1,   // [32]
    const float* __restrict__ W2,   // [1,32]
    const float* __restrict__ b2,   // [1]
    float* __restrict__ out,
    int G)
{
    __shared__ float sW1[64];
    __shared__ float sb1[32];
    __shared__ float sW2[32];
    __shared__ float sb2;

    const int t = threadIdx.x;
    // Independent of the reduce: issue BEFORE the grid-dependency sync so the
    // cold DRAM fetch of the weights overlaps the reduce's tail.
    if (t < 64)        sW1[t]      = W1[t];
    else if (t < 96)   sb1[t - 64] = b1[t - 64];
    else               sW2[t - 96] = W2[t - 96];
    if (t == 0)        sb2 = *b2;

#if __CUDA_ARCH__ >= 900
    cudaGridDependencySynchronize();   // reduce fully done + memory visible
#endif
    __syncthreads();

    int g = blockIdx.x * blockDim.x + t;
    if (g >= G) return;

    float cc = g_cnt[g];
    float t0 = g_s0[g];
    float t1 = g_s1[g];
    g_cnt[g] = 0.f; g_s0[g] = 0.f; g_s1[g] = 0.f;   // reset for next replay

    float denom = fmaxf(cc, 1.f);
    float f0 = 1.f - t0 / denom;
    float f1 = 1.f - t1 / denom;

    float acc = sb2;
    #pragma unroll
    for (int j = 0; j < 32; ++j) {
        float h = fmaf(f0, sW1[2 * j], fmaf(f1, sW1[2 * j + 1], sb1[j]));
        h   = fmaxf(h, 0.f);
        acc = fmaf(sW2[j], h, acc);
    }
    float score = 1.f / (1.f + __expf(-acc));
    out[g] = (cc > 0.f) ? score : 0.f;
}

extern "C" void kernel_launch(void* const* d_in, const int* in_sizes, int n_in,
                              void* d_out, int out_size)
{
    // order: node_features, batch, graph_embedding, W1, b1, W2, b2
    const float* nf    = (const float*)d_in[0];
    const int*   batch = (const int*)d_in[1];
    const float* W1    = (const float*)d_in[3];
    const float* b1    = (const float*)d_in[4];
    const float* W2    = (const float*)d_in[5];
    const float* b2    = (const float*)d_in[6];
    float*       out   = (float*)d_out;

    int N = in_sizes[1];
    int G = in_sizes[2] / F_DIM;
    if (G <= 0 || G > MAXG) G = out_size;

    int rb = (N + 255) / 256;
    reduce_kernel<<<rb, 256>>>(nf, batch, N);

    // PDL launch: finalize may begin its prologue while reduce's last wave runs.
    int fb = (G + 127) / 128;
    cudaLaunchConfig_t cfg = {};
    cfg.gridDim  = dim3((unsigned)fb, 1, 1);
    cfg.blockDim = dim3(128, 1, 1);
    cfg.dynamicSmemBytes = 0;
    cfg.stream = 0;   // same (legacy default) stream as the <<<>>> launch
    cudaLaunchAttribute attr[1];
    attr[0].id = cudaLaunchAttributeProgrammaticStreamSerialization;
    attr[0].val.programmaticStreamSerializationAllowed = 1;
    cfg.attrs = attr;
    cfg.numAttrs = 1;
    cudaLaunchKernelEx(&cfg, finalize_kernel, W1, b1, W2, b2, out, G);
}